// round 1
// baseline (speedup 1.0000x reference)
#include <cuda_runtime.h>

#define NTOT 40960
#define ETOT 81920
#define GTOT 1024
#define NC   512     // distinct edge-feature combos (8^3)
#define DIN  64
#define DOUT 32

// ---------------- scratch (device globals: no allocation allowed) ----------
__device__ __align__(16) float g_x[NTOT * DIN];          // node embeddings
__device__ __align__(16) float g_eu[NC * 16];            // unique edge embeds
__device__ __align__(16) float g_h1[NC * 1024];
__device__ __align__(16) float g_h2[NC * 256];
__device__ __align__(16) float g_W[(NC + 1) * 2048];     // 512 combo mats + root
__device__ __align__(16) float g_dense[GTOT * 1280];     // [G,40,32]
__device__ __align__(16) float g_f1[GTOT * 256];
__device__ __align__(16) float g_f2[GTOT * 128];
__device__ int g_combo[ETOT];
__device__ int g_hist[NC];
__device__ int g_off[NC];
__device__ int g_cursor[NC];
__device__ int g_sorted[ETOT];

// ---------------- small prep kernels ---------------------------------------
__global__ void zero_hist_k() {
    if (threadIdx.x < NC) g_hist[threadIdx.x] = 0;
}

// x[n,d] = sum_c atom_emb[c, nf[n,c], d]
__global__ void encode_x_k(const int* __restrict__ nf,
                           const float* __restrict__ atom) {
    __shared__ int s_nf[4][9];
    const int tid = threadIdx.x;
    if (tid < 36) {
        int nl = tid / 9, c = tid % 9;
        s_nf[nl][c] = nf[(blockIdx.x * 4 + nl) * 9 + c];
    }
    __syncthreads();
    const int nl = tid >> 6;
    const int d  = tid & 63;
    const int n  = blockIdx.x * 4 + nl;
    float acc = 0.f;
#pragma unroll
    for (int c = 0; c < 9; c++)
        acc += atom[(c * 128 + s_nf[nl][c]) * 64 + d];
    g_x[n * 64 + d] = acc;
}

__global__ void combo_k(const int* __restrict__ ef) {
    int e = blockIdx.x * 256 + threadIdx.x;
    int c = ef[e * 3] * 64 + ef[e * 3 + 1] * 8 + ef[e * 3 + 2];
    g_combo[e] = c;
    atomicAdd(&g_hist[c], 1);
}

__global__ void scan_k() {   // 1 block, 512 threads
    __shared__ int s[NC];
    int t = threadIdx.x;
    s[t] = g_hist[t];
    __syncthreads();
    for (int d = 1; d < NC; d <<= 1) {
        int v = (t >= d) ? s[t - d] : 0;
        __syncthreads();
        s[t] += v;
        __syncthreads();
    }
    int excl = s[t] - g_hist[t];
    g_off[t] = excl;
    g_cursor[t] = excl;
}

__global__ void scatter_k() {
    int e = blockIdx.x * 256 + threadIdx.x;
    int c = g_combo[e];
    int p = atomicAdd(&g_cursor[c], 1);
    g_sorted[p] = e;
}

// e_u[c,j] = sum of 3 bond embeddings decoded from combo id
__global__ void eu_k(const float* __restrict__ bond) {
    int idx = blockIdx.x * 256 + threadIdx.x;   // 512*16 = 8192
    if (idx >= NC * 16) return;
    int c = idx >> 4, j = idx & 15;
    g_eu[idx] = bond[(0 * 8 + (c >> 6)) * 16 + j]
              + bond[(1 * 8 + ((c >> 3) & 7)) * 16 + j]
              + bond[(2 * 8 + (c & 7)) * 16 + j];
}

__global__ void copy_root_k(const float* __restrict__ root) {
    int i = blockIdx.x * 256 + threadIdx.x;
    if (i < 2048) g_W[NC * 2048 + i] = root[i];
}

__global__ void bias_init_k(const float* __restrict__ cb) {
    int i = blockIdx.x * 256 + threadIdx.x;   // GTOT*1280 total
    g_dense[i] = cb[i & 31];
}

// ---------------- generic tiled SGEMM: C = op(A[M,K] @ B[K,N] (+bias)) -----
// BM=BN=64, BK=16, 256 threads, 4x4 per thread. M%64==0, N%64==0, K%16==0.
template <bool RELU, bool HASBIAS>
__global__ void gemm_k(const float* __restrict__ A, const float* __restrict__ B,
                       const float* __restrict__ bias, float* __restrict__ C,
                       int M, int N, int K, int ldb) {
    __shared__ float As[16][64];
    __shared__ float Bs[16][64];
    const int tid  = threadIdx.x;
    const int trow = tid >> 4;          // 0..15
    const int tcol = tid & 15;          // 0..15
    const int lr = tid >> 2;            // 0..63
    const int lk = (tid & 3) << 2;      // 0,4,8,12
    const int bk = tid >> 4;            // 0..15
    const int bn = (tid & 15) << 2;     // 0..60
    const float* Ab = A + (size_t)blockIdx.y * 64 * K;
    const float* Bb = B + blockIdx.x * 64;
    float acc[4][4] = {};
    for (int kt = 0; kt < K; kt += 16) {
        float4 av = *(const float4*)(Ab + lr * K + kt + lk);
        As[lk + 0][lr] = av.x; As[lk + 1][lr] = av.y;
        As[lk + 2][lr] = av.z; As[lk + 3][lr] = av.w;
        float4 bv = *(const float4*)(Bb + (size_t)(kt + bk) * ldb + bn);
        *(float4*)&Bs[bk][bn] = bv;
        __syncthreads();
#pragma unroll
        for (int k = 0; k < 16; k++) {
            float4 a = *(const float4*)&As[k][trow << 2];
            float4 b = *(const float4*)&Bs[k][tcol << 2];
            float ar[4] = {a.x, a.y, a.z, a.w};
            float br[4] = {b.x, b.y, b.z, b.w};
#pragma unroll
            for (int i = 0; i < 4; i++)
#pragma unroll
                for (int j = 0; j < 4; j++)
                    acc[i][j] += ar[i] * br[j];
        }
        __syncthreads();
    }
    int row0 = blockIdx.y * 64 + (trow << 2);
    int col0 = blockIdx.x * 64 + (tcol << 2);
    float4 bb = make_float4(0.f, 0.f, 0.f, 0.f);
    if (HASBIAS) bb = *(const float4*)(bias + col0);
#pragma unroll
    for (int i = 0; i < 4; i++) {
        float4 o;
        o.x = acc[i][0] + bb.x; o.y = acc[i][1] + bb.y;
        o.z = acc[i][2] + bb.z; o.w = acc[i][3] + bb.w;
        if (RELU) {
            o.x = fmaxf(o.x, 0.f); o.y = fmaxf(o.y, 0.f);
            o.z = fmaxf(o.z, 0.f); o.w = fmaxf(o.w, 0.f);
        }
        *(float4*)(C + (size_t)(row0 + i) * N + col0) = o;
    }
}

// ---------------- message passing as per-combo GEMM + atomic scatter -------
// blocks [0,512): combo c, edges from sorted list, msg = x[src] @ W[c],
//                 atomicAdd into dense[dst].
// blocks [512,832): "self edges" applying W[512] = root to every node.
__global__ void msg_k(const int* __restrict__ ei) {
    __shared__ float Ws[2048];
    __shared__ float Xs[128 * 65];
    __shared__ int Srcs[128];
    __shared__ int Dsts[128];
    const int tid = threadIdx.x;
    int c, start, cnt;
    bool is_root = (blockIdx.x >= NC);
    if (!is_root) { c = blockIdx.x; start = g_off[c]; cnt = g_hist[c]; }
    else          { c = NC; start = (blockIdx.x - NC) * 128; cnt = 128; }
    if (cnt == 0) return;
    const float* Wp = g_W + c * 2048;
    for (int i = tid; i < 512; i += 256)
        ((float4*)Ws)[i] = ((const float4*)Wp)[i];

    for (int base = 0; base < cnt; base += 128) {
        int nloc = min(128, cnt - base);
        __syncthreads();    // Ws visible (iter 0) / prior compute done
        if (!is_root) {
            for (int j = tid; j < nloc; j += 256) {
                int e = g_sorted[start + base + j];
                Srcs[j] = ei[e];
                Dsts[j] = ei[ETOT + e];
            }
        } else {
            for (int j = tid; j < nloc; j += 256) {
                Srcs[j] = start + j;
                Dsts[j] = start + j;
            }
        }
        __syncthreads();
        for (int idx = tid; idx < nloc * 64; idx += 256) {
            int j = idx >> 6, k = idx & 63;
            Xs[j * 65 + k] = g_x[Srcs[j] * 64 + k];
        }
        __syncthreads();
        const int e0 = (tid >> 3) * 4;   // 4 edges
        const int c0 = (tid & 7) * 4;    // 4 cols
        float acc[4][4] = {};
#pragma unroll 8
        for (int k = 0; k < 64; k++) {
            float4 wv = *(const float4*)&Ws[k * 32 + c0];
#pragma unroll
            for (int i = 0; i < 4; i++) {
                float xv = Xs[(e0 + i) * 65 + k];
                acc[i][0] += xv * wv.x; acc[i][1] += xv * wv.y;
                acc[i][2] += xv * wv.z; acc[i][3] += xv * wv.w;
            }
        }
#pragma unroll
        for (int i = 0; i < 4; i++) {
            int j = e0 + i;
            if (j < nloc) {
                float* dp = &g_dense[Dsts[j] * 32 + c0];
                atomicAdd(dp + 0, acc[i][0]); atomicAdd(dp + 1, acc[i][1]);
                atomicAdd(dp + 2, acc[i][2]); atomicAdd(dp + 3, acc[i][3]);
            }
        }
    }
}

// ---------------- fused readout tail: 128 -> 32 -> 8 -> 1 ------------------
// one warp per graph, 8 warps per block
__global__ void head_k(const float* __restrict__ mW3, const float* __restrict__ mb3,
                       const float* __restrict__ mW4, const float* __restrict__ mb4,
                       const float* __restrict__ mW5, const float* __restrict__ mb5,
                       float* __restrict__ out) {
    __shared__ float W3[128 * 32];
    __shared__ float W4[32 * 8];
    __shared__ float W5[8];
    __shared__ float B3[32], B4[8], B5;
    const int tid = threadIdx.x;
    for (int i = tid; i < 4096; i += 256) W3[i] = mW3[i];
    if (tid < 256) W4[tid] = mW4[tid];
    if (tid < 32) B3[tid] = mb3[tid];
    if (tid < 8)  { W5[tid] = mW5[tid]; B4[tid] = mb4[tid]; }
    if (tid == 0) B5 = mb5[0];
    __syncthreads();
    const int warp = tid >> 5, lane = tid & 31;
    const int g = blockIdx.x * 8 + warp;
    const float* f2 = g_f2 + g * 128;
    float acc = B3[lane];
#pragma unroll 4
    for (int k = 0; k < 128; k++)
        acc += f2[k] * W3[k * 32 + lane];
    acc = fmaxf(acc, 0.f);                         // f3[lane]
    float acc4 = (lane < 8) ? B4[lane] : 0.f;
#pragma unroll
    for (int k = 0; k < 32; k++) {
        float f3k = __shfl_sync(0xffffffffu, acc, k);
        if (lane < 8) acc4 += f3k * W4[k * 8 + lane];
    }
    acc4 = fmaxf(acc4, 0.f);                       // f4[lane] (lanes 0..7)
    float r = 0.f;
#pragma unroll
    for (int k = 0; k < 8; k++) {
        float f4k = __shfl_sync(0xffffffffu, acc4, k);
        r += f4k * W5[k];
    }
    if (lane == 0) out[g] = r + B5;
}

// ---------------- launch ----------------------------------------------------
extern "C" void kernel_launch(void* const* d_in, const int* in_sizes, int n_in,
                              void* d_out, int out_size) {
    (void)in_sizes; (void)n_in; (void)out_size;
    const int*   nf   = (const int*)d_in[0];
    const int*   ef   = (const int*)d_in[1];
    const int*   ei   = (const int*)d_in[2];
    const float* atom = (const float*)d_in[4];
    const float* bond = (const float*)d_in[5];
    const float* gW1  = (const float*)d_in[6];
    const float* gW2  = (const float*)d_in[7];
    const float* gW3  = (const float*)d_in[8];
    const float* root = (const float*)d_in[9];
    const float* cb   = (const float*)d_in[10];
    const float* mW1  = (const float*)d_in[11];
    const float* mb1  = (const float*)d_in[12];
    const float* mW2  = (const float*)d_in[13];
    const float* mb2  = (const float*)d_in[14];
    const float* mW3  = (const float*)d_in[15];
    const float* mb3  = (const float*)d_in[16];
    const float* mW4  = (const float*)d_in[17];
    const float* mb4  = (const float*)d_in[18];
    const float* mW5  = (const float*)d_in[19];
    const float* mb5  = (const float*)d_in[20];
    float* out = (float*)d_out;

    float *p_eu, *p_h1, *p_h2, *p_W, *p_dense, *p_f1, *p_f2;
    cudaGetSymbolAddress((void**)&p_eu,    g_eu);
    cudaGetSymbolAddress((void**)&p_h1,    g_h1);
    cudaGetSymbolAddress((void**)&p_h2,    g_h2);
    cudaGetSymbolAddress((void**)&p_W,     g_W);
    cudaGetSymbolAddress((void**)&p_dense, g_dense);
    cudaGetSymbolAddress((void**)&p_f1,    g_f1);
    cudaGetSymbolAddress((void**)&p_f2,    g_f2);

    zero_hist_k<<<1, 512>>>();
    encode_x_k<<<NTOT / 4, 256>>>(nf, atom);
    combo_k<<<ETOT / 256, 256>>>(ef);
    scan_k<<<1, NC>>>();
    scatter_k<<<ETOT / 256, 256>>>();
    eu_k<<<32, 256>>>(bond);

    // unique-combo edge MLP: 512x16 -> 1024 -> 256 -> 2048
    gemm_k<true,  false><<<dim3(16, 8), 256>>>(p_eu, gW1, nullptr, p_h1, NC, 1024, 16, 1024);
    gemm_k<true,  false><<<dim3(4,  8), 256>>>(p_h1, gW2, nullptr, p_h2, NC, 256, 1024, 256);
    gemm_k<false, false><<<dim3(32, 8), 256>>>(p_h2, gW3, nullptr, p_W,  NC, 2048, 256, 2048);

    copy_root_k<<<8, 256>>>(root);
    bias_init_k<<<(GTOT * 1280) / 256, 256>>>(cb);
    msg_k<<<NC + NTOT / 128, 256>>>(ei);

    // readout: dense[1024,1280] @ mW1[0:1280,:256] -> 256 -> 128
    gemm_k<true, true><<<dim3(4, 16), 256>>>(p_dense, mW1, mb1, p_f1, GTOT, 256, 1280, 256);
    gemm_k<true, true><<<dim3(2, 16), 256>>>(p_f1,    mW2, mb2, p_f2, GTOT, 128, 256,  128);
    head_k<<<GTOT / 8, 256>>>(mW3, mb3, mW4, mb4, mW5, mb5, out);
}

// round 4
// speedup vs baseline: 1.5954x; 1.5954x over previous
#include <cuda_runtime.h>

#define NTOT 40960
#define ETOT 81920
#define GTOT 1024
#define NC   512

// ---------------- scratch ---------------------------------------------------
__device__ __align__(16) float g_x[NTOT * 64];
__device__ __align__(16) float g_h1[NC * 1024];
__device__ __align__(16) float g_h2[NC * 256];
__device__ __align__(16) float g_W[NC * 2048];
__device__ __align__(16) float g_dense[GTOT * 1280];
__device__ __align__(16) float g_f1[GTOT * 256];
__device__ __align__(16) float g_f2[GTOT * 128];
__device__ __align__(16) float g_bias1[256];
__device__ int g_combo[ETOT];
__device__ int g_hist[NC];
__device__ int g_off[NC];
__device__ int g_cursor[NC];
__device__ int g_sorted[ETOT];

// ---------------- prep ------------------------------------------------------
__global__ void encode_x_k(const int* __restrict__ nf,
                           const float* __restrict__ atom) {
    __shared__ int s_nf[4][9];
    const int tid = threadIdx.x;
    if (tid < 36) {
        int nl = tid / 9, c = tid % 9;
        s_nf[nl][c] = nf[(blockIdx.x * 4 + nl) * 9 + c];
    }
    __syncthreads();
    const int nl = tid >> 6;
    const int d  = tid & 63;
    const int n  = blockIdx.x * 4 + nl;
    float acc = 0.f;
#pragma unroll
    for (int c = 0; c < 9; c++)
        acc += atom[(c * 128 + s_nf[nl][c]) * 64 + d];
    g_x[n * 64 + d] = acc;
}

__global__ void combo_k(const int* __restrict__ ef) {
    int e = blockIdx.x * 256 + threadIdx.x;
    int c = ef[e * 3] * 64 + ef[e * 3 + 1] * 8 + ef[e * 3 + 2];
    g_combo[e] = c;
    atomicAdd(&g_hist[c], 1);
}

__global__ void scan_k() {    // 1 block, 512 threads, warp-shuffle scan
    __shared__ int wsum[16];
    int t = threadIdx.x;
    int v = g_hist[t];
    int lane = t & 31, w = t >> 5;
    int s = v;
#pragma unroll
    for (int d = 1; d < 32; d <<= 1) {
        int u = __shfl_up_sync(0xffffffffu, s, d);
        if (lane >= d) s += u;
    }
    if (lane == 31) wsum[w] = s;
    __syncthreads();
    if (t < 16) {
        int x = wsum[t];
#pragma unroll
        for (int d = 1; d < 16; d <<= 1) {
            int u = __shfl_up_sync(0xffffu, x, d);
            if (t >= d) x += u;
        }
        wsum[t] = x;
    }
    __syncthreads();
    int off = (w > 0 ? wsum[w - 1] : 0) + s - v;   // exclusive prefix
    g_off[t] = off;
    g_cursor[t] = off;
}

__global__ void scatter_k() {
    int e = blockIdx.x * 256 + threadIdx.x;
    int c = g_combo[e];
    int p = atomicAdd(&g_cursor[c], 1);
    g_sorted[p] = e;
}

// ---------------- E1: h1 = relu(eu @ gW1), eu computed on the fly -----------
__global__ void gemmE1_k(const float* __restrict__ bond,
                         const float* __restrict__ gW1) {
    __shared__ float bnd[384];
    __shared__ float As[16][64];
    __shared__ float Bs[16][64];
    const int tid = threadIdx.x;
    for (int i = tid; i < 384; i += 256) bnd[i] = bond[i];   // FIXED: full table
    __syncthreads();
    // A tile: rows = 64 combos, cols = 16
    for (int idx = tid; idx < 1024; idx += 256) {
        int r = idx >> 4, j = idx & 15;
        int c = blockIdx.y * 64 + r;
        As[j][r] = bnd[(c >> 6) * 16 + j]
                 + bnd[128 + ((c >> 3) & 7) * 16 + j]
                 + bnd[256 + (c & 7) * 16 + j];
    }
    {
        int bk = tid >> 4, bn = (tid & 15) << 2;
        *(float4*)&Bs[bk][bn] = *(const float4*)(gW1 + (size_t)bk * 1024 + blockIdx.x * 64 + bn);
    }
    __syncthreads();
    const int trow = tid >> 4, tcol = tid & 15;
    float acc[4][4] = {};
#pragma unroll
    for (int k = 0; k < 16; k++) {
        float4 a = *(const float4*)&As[k][trow << 2];
        float4 b = *(const float4*)&Bs[k][tcol << 2];
        float ar[4] = {a.x, a.y, a.z, a.w};
        float br[4] = {b.x, b.y, b.z, b.w};
#pragma unroll
        for (int i = 0; i < 4; i++)
#pragma unroll
            for (int j = 0; j < 4; j++)
                acc[i][j] += ar[i] * br[j];
    }
    int row0 = blockIdx.y * 64 + (trow << 2);
    int col0 = blockIdx.x * 64 + (tcol << 2);
#pragma unroll
    for (int i = 0; i < 4; i++) {
        float4 o;
        o.x = fmaxf(acc[i][0], 0.f); o.y = fmaxf(acc[i][1], 0.f);
        o.z = fmaxf(acc[i][2], 0.f); o.w = fmaxf(acc[i][3], 0.f);
        *(float4*)(g_h1 + (size_t)(row0 + i) * 1024 + col0) = o;
    }
}

// ---------------- split-K SGEMM, atomicAdd epilogue -------------------------
// grid: (N/64, M/64, K/KC). optional relu applied to A elements on load.
template <bool RELU_A>
__global__ void gemm_k(const float* __restrict__ A, const float* __restrict__ B,
                       float* __restrict__ C, int N, int lda, int ldb, int KC) {
    __shared__ float As[16][64];
    __shared__ float Bs[16][64];
    const int tid  = threadIdx.x;
    const int trow = tid >> 4;
    const int tcol = tid & 15;
    const int lr = tid >> 2;
    const int lk = (tid & 3) << 2;
    const int bk = tid >> 4;
    const int bn = (tid & 15) << 2;
    const float* Ab = A + (size_t)blockIdx.y * 64 * lda;
    const float* Bb = B + blockIdx.x * 64;
    const int k0 = blockIdx.z * KC;
    float acc[4][4] = {};
    for (int kt = k0; kt < k0 + KC; kt += 16) {
        float4 av = *(const float4*)(Ab + (size_t)lr * lda + kt + lk);
        if (RELU_A) {
            av.x = fmaxf(av.x, 0.f); av.y = fmaxf(av.y, 0.f);
            av.z = fmaxf(av.z, 0.f); av.w = fmaxf(av.w, 0.f);
        }
        As[lk + 0][lr] = av.x; As[lk + 1][lr] = av.y;
        As[lk + 2][lr] = av.z; As[lk + 3][lr] = av.w;
        *(float4*)&Bs[bk][bn] = *(const float4*)(Bb + (size_t)(kt + bk) * ldb + bn);
        __syncthreads();
#pragma unroll
        for (int k = 0; k < 16; k++) {
            float4 a = *(const float4*)&As[k][trow << 2];
            float4 b = *(const float4*)&Bs[k][tcol << 2];
            float ar[4] = {a.x, a.y, a.z, a.w};
            float br[4] = {b.x, b.y, b.z, b.w};
#pragma unroll
            for (int i = 0; i < 4; i++)
#pragma unroll
                for (int j = 0; j < 4; j++)
                    acc[i][j] += ar[i] * br[j];
        }
        __syncthreads();
    }
    int row0 = blockIdx.y * 64 + (trow << 2);
    int col0 = blockIdx.x * 64 + (tcol << 2);
#pragma unroll
    for (int i = 0; i < 4; i++) {
        float* cp = C + (size_t)(row0 + i) * N + col0;
        atomicAdd(cp + 0, acc[i][0]); atomicAdd(cp + 1, acc[i][1]);
        atomicAdd(cp + 2, acc[i][2]); atomicAdd(cp + 3, acc[i][3]);
    }
}

// ---------------- bias1 = mb1 + (conv_bias tiled over 1280) @ mW1 -----------
__global__ void biasR1_k(const float* __restrict__ mW1,
                         const float* __restrict__ mb1,
                         const float* __restrict__ cb) {
    int c = threadIdx.x;
    int k0 = blockIdx.x * 128;
    float acc = 0.f;
    for (int k = k0; k < k0 + 128; k++)
        acc += cb[k & 31] * mW1[(size_t)k * 256 + c];
    if (blockIdx.x == 0) acc += mb1[c];
    atomicAdd(&g_bias1[c], acc);
}

__global__ void f1init_k() {
    int i = blockIdx.x * 256 + threadIdx.x;
    g_f1[i] = g_bias1[i & 255];
}

// ---------------- message passing -------------------------------------------
// root part: dense[n,:] = x[n,:] @ root   (plain stores, initializes dense)
__global__ void msg_root_k(const float* __restrict__ root) {
    __shared__ float Ws[2048];
    __shared__ float Xs[128 * 68];
    const int tid = threadIdx.x;
    const int n0 = blockIdx.x * 128;
    for (int i = tid; i < 512; i += 256)
        ((float4*)Ws)[i] = ((const float4*)root)[i];
    for (int idx = tid; idx < 128 * 16; idx += 256) {
        int j = idx >> 4, kq = idx & 15;
        ((float4*)(Xs + j * 68))[kq] = ((const float4*)(g_x + (size_t)(n0 + j) * 64))[kq];
    }
    __syncthreads();
    const int e0 = (tid >> 3) << 2;
    const int c0 = (tid & 7) << 2;
    float acc[4][4] = {};
#pragma unroll 4
    for (int kk = 0; kk < 64; kk += 4) {
        float4 w0 = *(const float4*)&Ws[(kk + 0) * 32 + c0];
        float4 w1 = *(const float4*)&Ws[(kk + 1) * 32 + c0];
        float4 w2 = *(const float4*)&Ws[(kk + 2) * 32 + c0];
        float4 w3 = *(const float4*)&Ws[(kk + 3) * 32 + c0];
#pragma unroll
        for (int i = 0; i < 4; i++) {
            float4 xv = *(const float4*)&Xs[(e0 + i) * 68 + kk];
            acc[i][0] += xv.x * w0.x + xv.y * w1.x + xv.z * w2.x + xv.w * w3.x;
            acc[i][1] += xv.x * w0.y + xv.y * w1.y + xv.z * w2.y + xv.w * w3.y;
            acc[i][2] += xv.x * w0.z + xv.y * w1.z + xv.z * w2.z + xv.w * w3.z;
            acc[i][3] += xv.x * w0.w + xv.y * w1.w + xv.z * w2.w + xv.w * w3.w;
        }
    }
#pragma unroll
    for (int i = 0; i < 4; i++) {
        float4 o = make_float4(acc[i][0], acc[i][1], acc[i][2], acc[i][3]);
        *(float4*)(g_dense + (size_t)(n0 + e0 + i) * 32 + c0) = o;
    }
}

// combo part: per-combo GEMM over sorted edges, atomicAdd into dense
__global__ void msg_combo_k(const int* __restrict__ ei) {
    __shared__ float Ws[2048];
    __shared__ float Xs[128 * 68];
    __shared__ int Srcs[128];
    __shared__ int Dsts[128];
    const int tid = threadIdx.x;
    const int c = blockIdx.x;
    const int start = g_off[c];
    const int cnt = g_hist[c];
    if (cnt == 0) return;
    const float* Wp = g_W + (size_t)c * 2048;
    for (int i = tid; i < 512; i += 256)
        ((float4*)Ws)[i] = ((const float4*)Wp)[i];

    for (int base = 0; base < cnt; base += 128) {
        int nloc = min(128, cnt - base);
        __syncthreads();
        for (int j = tid; j < nloc; j += 256) {
            int e = g_sorted[start + base + j];
            Srcs[j] = ei[e];
            Dsts[j] = ei[ETOT + e];
        }
        __syncthreads();
        for (int idx = tid; idx < nloc * 16; idx += 256) {
            int j = idx >> 4, kq = idx & 15;
            ((float4*)(Xs + j * 68))[kq] = ((const float4*)(g_x + (size_t)Srcs[j] * 64))[kq];
        }
        __syncthreads();
        const int e0 = (tid >> 3) << 2;
        const int c0 = (tid & 7) << 2;
        float acc[4][4] = {};
#pragma unroll 4
        for (int kk = 0; kk < 64; kk += 4) {
            float4 w0 = *(const float4*)&Ws[(kk + 0) * 32 + c0];
            float4 w1 = *(const float4*)&Ws[(kk + 1) * 32 + c0];
            float4 w2 = *(const float4*)&Ws[(kk + 2) * 32 + c0];
            float4 w3 = *(const float4*)&Ws[(kk + 3) * 32 + c0];
#pragma unroll
            for (int i = 0; i < 4; i++) {
                float4 xv = *(const float4*)&Xs[(e0 + i) * 68 + kk];
                acc[i][0] += xv.x * w0.x + xv.y * w1.x + xv.z * w2.x + xv.w * w3.x;
                acc[i][1] += xv.x * w0.y + xv.y * w1.y + xv.z * w2.y + xv.w * w3.y;
                acc[i][2] += xv.x * w0.z + xv.y * w1.z + xv.z * w2.z + xv.w * w3.z;
                acc[i][3] += xv.x * w0.w + xv.y * w1.w + xv.z * w2.w + xv.w * w3.w;
            }
        }
#pragma unroll
        for (int i = 0; i < 4; i++) {
            int j = e0 + i;
            if (j < nloc) {
                float* dp = &g_dense[(size_t)Dsts[j] * 32 + c0];
                atomicAdd(dp + 0, acc[i][0]); atomicAdd(dp + 1, acc[i][1]);
                atomicAdd(dp + 2, acc[i][2]); atomicAdd(dp + 3, acc[i][3]);
            }
        }
    }
}

// ---------------- readout tail: relu(f2+mb2) -> 32 -> 8 -> 1 ----------------
__global__ void head_k(const float* __restrict__ mW3, const float* __restrict__ mb3,
                       const float* __restrict__ mW4, const float* __restrict__ mb4,
                       const float* __restrict__ mW5, const float* __restrict__ mb5,
                       const float* __restrict__ mb2, float* __restrict__ out) {
    __shared__ float W3[128 * 32];
    __shared__ float W4[32 * 8];
    __shared__ float W5[8];
    __shared__ float B3[32], B4[8], B2[128], B5;
    const int tid = threadIdx.x;
    for (int i = tid; i < 4096; i += 256) W3[i] = mW3[i];
    if (tid < 256) W4[tid] = mW4[tid];
    if (tid < 128) B2[tid] = mb2[tid];
    if (tid < 32) B3[tid] = mb3[tid];
    if (tid < 8)  { W5[tid] = mW5[tid]; B4[tid] = mb4[tid]; }
    if (tid == 0) B5 = mb5[0];
    __syncthreads();
    const int warp = tid >> 5, lane = tid & 31;
    const int g = blockIdx.x * 8 + warp;
    const float* f2 = g_f2 + (size_t)g * 128;
    float acc = B3[lane];
#pragma unroll 4
    for (int k = 0; k < 128; k++) {
        float v = fmaxf(f2[k] + B2[k], 0.f);
        acc += v * W3[k * 32 + lane];
    }
    acc = fmaxf(acc, 0.f);
    float acc4 = (lane < 8) ? B4[lane] : 0.f;
#pragma unroll
    for (int k = 0; k < 32; k++) {
        float f3k = __shfl_sync(0xffffffffu, acc, k);
        if (lane < 8) acc4 += f3k * W4[k * 8 + lane];
    }
    acc4 = fmaxf(acc4, 0.f);
    float r = 0.f;
#pragma unroll
    for (int k = 0; k < 8; k++) {
        float f4k = __shfl_sync(0xffffffffu, acc4, k);
        r += f4k * W5[k];
    }
    if (lane == 0) out[g] = r + B5;
}

// ---------------- launch ----------------------------------------------------
extern "C" void kernel_launch(void* const* d_in, const int* in_sizes, int n_in,
                              void* d_out, int out_size) {
    (void)in_sizes; (void)n_in; (void)out_size;
    const int*   nf   = (const int*)d_in[0];
    const int*   ef   = (const int*)d_in[1];
    const int*   ei   = (const int*)d_in[2];
    const float* atom = (const float*)d_in[4];
    const float* bond = (const float*)d_in[5];
    const float* gW1  = (const float*)d_in[6];
    const float* gW2  = (const float*)d_in[7];
    const float* gW3  = (const float*)d_in[8];
    const float* root = (const float*)d_in[9];
    const float* cb   = (const float*)d_in[10];
    const float* mW1  = (const float*)d_in[11];
    const float* mb1  = (const float*)d_in[12];
    const float* mW2  = (const float*)d_in[13];
    const float* mb2  = (const float*)d_in[14];
    const float* mW3  = (const float*)d_in[15];
    const float* mb3  = (const float*)d_in[16];
    const float* mW4  = (const float*)d_in[17];
    const float* mb4  = (const float*)d_in[18];
    const float* mW5  = (const float*)d_in[19];
    const float* mb5  = (const float*)d_in[20];
    float* out = (float*)d_out;

    float *p_h1, *p_h2, *p_W, *p_dense, *p_f1, *p_f2, *p_b1;
    int* p_hist;
    cudaGetSymbolAddress((void**)&p_h1,    g_h1);
    cudaGetSymbolAddress((void**)&p_h2,    g_h2);
    cudaGetSymbolAddress((void**)&p_W,     g_W);
    cudaGetSymbolAddress((void**)&p_dense, g_dense);
    cudaGetSymbolAddress((void**)&p_f1,    g_f1);
    cudaGetSymbolAddress((void**)&p_f2,    g_f2);
    cudaGetSymbolAddress((void**)&p_b1,    g_bias1);
    cudaGetSymbolAddress((void**)&p_hist,  g_hist);

    static cudaStream_t s1 = nullptr;
    static cudaEvent_t evFork, evW, evF;
    if (!s1) {
        cudaStreamCreateWithFlags(&s1, cudaStreamNonBlocking);
        cudaEventCreateWithFlags(&evFork, cudaEventDisableTiming);
        cudaEventCreateWithFlags(&evW, cudaEventDisableTiming);
        cudaEventCreateWithFlags(&evF, cudaEventDisableTiming);
    }

    // fork side stream: edge-weight MLP + readout bias precompute
    cudaEventRecord(evFork, 0);
    cudaStreamWaitEvent(s1, evFork, 0);

    cudaMemsetAsync(p_h2, 0, NC * 256 * sizeof(float), s1);
    cudaMemsetAsync(p_W,  0, NC * 2048 * sizeof(float), s1);
    cudaMemsetAsync(p_b1, 0, 256 * sizeof(float), s1);
    gemmE1_k<<<dim3(16, 8), 256, 0, s1>>>(bond, gW1);
    gemm_k<false><<<dim3(4, 8, 8),  256, 0, s1>>>(p_h1, gW2, p_h2, 256, 1024, 256, 128);
    gemm_k<true ><<<dim3(32, 8, 4), 256, 0, s1>>>(p_h2, gW3, p_W, 2048, 256, 2048, 64);
    cudaEventRecord(evW, s1);
    biasR1_k<<<10, 256, 0, s1>>>(mW1, mb1, cb);
    f1init_k<<<1024, 256, 0, s1>>>();
    cudaMemsetAsync(p_f2, 0, GTOT * 128 * sizeof(float), s1);
    cudaEventRecord(evF, s1);

    // main stream: node encode + root GEMM + edge sort
    cudaMemsetAsync(p_hist, 0, NC * sizeof(int), 0);
    encode_x_k<<<NTOT / 4, 256>>>(nf, atom);
    msg_root_k<<<NTOT / 128, 256>>>(root);
    combo_k<<<ETOT / 256, 256>>>(ef);
    scan_k<<<1, 512>>>();
    scatter_k<<<ETOT / 256, 256>>>();

    cudaStreamWaitEvent(0, evW, 0);
    msg_combo_k<<<NC, 256>>>(ei);

    cudaStreamWaitEvent(0, evF, 0);
    gemm_k<false><<<dim3(4, 16, 10), 256>>>(p_dense, mW1, p_f1, 256, 1280, 256, 128);
    gemm_k<true ><<<dim3(2, 16, 4),  256>>>(p_f1, mW2, p_f2, 128, 256, 128, 64);
    head_k<<<GTOT / 8, 256>>>(mW3, mb3, mW4, mb4, mW5, mb5, mb2, out);
}

// round 5
// speedup vs baseline: 1.7622x; 1.1046x over previous
#include <cuda_runtime.h>

#define NTOT 40960
#define ETOT 81920
#define GTOT 1024
#define NC   512

// ---------------- scratch ---------------------------------------------------
__device__ __align__(16) float g_x[NTOT * 64];
__device__ __align__(16) float g_h1[NC * 1024];
__device__ __align__(16) float g_h2[NC * 256];
__device__ __align__(16) float g_W[NC * 2048];
__device__ __align__(16) float g_dense[GTOT * 1280];
__device__ __align__(16) float g_f1[GTOT * 256];
__device__ __align__(16) float g_f2[GTOT * 128];
__device__ __align__(16) float g_bias1[256];
__device__ int g_combo[ETOT];
__device__ int g_hist[NC];
__device__ int g_off[NC];
__device__ int g_cursor[NC];
__device__ int g_sorted[ETOT];

// ---------------- zero fill (one kernel instead of 3 memsets) ---------------
__global__ void zero3_k(float4* a, int na, float4* b, int nb, float4* c, int nc) {
    const int stride = gridDim.x * blockDim.x;
    const float4 z = make_float4(0.f, 0.f, 0.f, 0.f);
    for (int i = blockIdx.x * blockDim.x + threadIdx.x; i < na; i += stride) a[i] = z;
    for (int i = blockIdx.x * blockDim.x + threadIdx.x; i < nb; i += stride) b[i] = z;
    for (int i = blockIdx.x * blockDim.x + threadIdx.x; i < nc; i += stride) c[i] = z;
}

// ---------------- prep ------------------------------------------------------
__global__ void encode_x_k(const int* __restrict__ nf,
                           const float* __restrict__ atom) {
    __shared__ int s_nf[4][9];
    const int tid = threadIdx.x;
    if (tid < 36) {
        int nl = tid / 9, c = tid % 9;
        s_nf[nl][c] = nf[(blockIdx.x * 4 + nl) * 9 + c];
    }
    __syncthreads();
    const int nl = tid >> 6;
    const int d  = tid & 63;
    const int n  = blockIdx.x * 4 + nl;
    float acc = 0.f;
#pragma unroll
    for (int c = 0; c < 9; c++)
        acc += atom[(c * 128 + s_nf[nl][c]) * 64 + d];
    g_x[n * 64 + d] = acc;
}

__global__ void combo_k(const int* __restrict__ ef) {
    int e = blockIdx.x * 256 + threadIdx.x;
    int c = ef[e * 3] * 64 + ef[e * 3 + 1] * 8 + ef[e * 3 + 2];
    g_combo[e] = c;
    atomicAdd(&g_hist[c], 1);
}

__global__ void scan_k() {    // 1 block, 512 threads, warp-shuffle scan
    __shared__ int wsum[16];
    int t = threadIdx.x;
    int v = g_hist[t];
    int lane = t & 31, w = t >> 5;
    int s = v;
#pragma unroll
    for (int d = 1; d < 32; d <<= 1) {
        int u = __shfl_up_sync(0xffffffffu, s, d);
        if (lane >= d) s += u;
    }
    if (lane == 31) wsum[w] = s;
    __syncthreads();
    if (t < 16) {
        int x = wsum[t];
#pragma unroll
        for (int d = 1; d < 16; d <<= 1) {
            int u = __shfl_up_sync(0xffffu, x, d);
            if (t >= d) x += u;
        }
        wsum[t] = x;
    }
    __syncthreads();
    int off = (w > 0 ? wsum[w - 1] : 0) + s - v;   // exclusive prefix
    g_off[t] = off;
    g_cursor[t] = off;
}

__global__ void scatter_k() {
    int e = blockIdx.x * 256 + threadIdx.x;
    int c = g_combo[e];
    int p = atomicAdd(&g_cursor[c], 1);
    g_sorted[p] = e;
}

// ---------------- E1: h1 = relu(eu @ gW1), eu computed on the fly -----------
__global__ void gemmE1_k(const float* __restrict__ bond,
                         const float* __restrict__ gW1) {
    __shared__ float bnd[384];
    __shared__ float As[16][64];
    __shared__ float Bs[16][64];
    const int tid = threadIdx.x;
    for (int i = tid; i < 384; i += 256) bnd[i] = bond[i];
    __syncthreads();
    for (int idx = tid; idx < 1024; idx += 256) {
        int r = idx >> 4, j = idx & 15;
        int c = blockIdx.y * 64 + r;
        As[j][r] = bnd[(c >> 6) * 16 + j]
                 + bnd[128 + ((c >> 3) & 7) * 16 + j]
                 + bnd[256 + (c & 7) * 16 + j];
    }
    {
        int bk = tid >> 4, bn = (tid & 15) << 2;
        *(float4*)&Bs[bk][bn] = *(const float4*)(gW1 + (size_t)bk * 1024 + blockIdx.x * 64 + bn);
    }
    __syncthreads();
    const int trow = tid >> 4, tcol = tid & 15;
    float acc[4][4] = {};
#pragma unroll
    for (int k = 0; k < 16; k++) {
        float4 a = *(const float4*)&As[k][trow << 2];
        float4 b = *(const float4*)&Bs[k][tcol << 2];
        float ar[4] = {a.x, a.y, a.z, a.w};
        float br[4] = {b.x, b.y, b.z, b.w};
#pragma unroll
        for (int i = 0; i < 4; i++)
#pragma unroll
            for (int j = 0; j < 4; j++)
                acc[i][j] += ar[i] * br[j];
    }
    int row0 = blockIdx.y * 64 + (trow << 2);
    int col0 = blockIdx.x * 64 + (tcol << 2);
#pragma unroll
    for (int i = 0; i < 4; i++) {
        float4 o;
        o.x = fmaxf(acc[i][0], 0.f); o.y = fmaxf(acc[i][1], 0.f);
        o.z = fmaxf(acc[i][2], 0.f); o.w = fmaxf(acc[i][3], 0.f);
        *(float4*)(g_h1 + (size_t)(row0 + i) * 1024 + col0) = o;
    }
}

// ---------------- split-K SGEMM, atomicAdd epilogue -------------------------
template <bool RELU_A>
__global__ void gemm_k(const float* __restrict__ A, const float* __restrict__ B,
                       float* __restrict__ C, int N, int lda, int ldb, int KC) {
    __shared__ float As[16][64];
    __shared__ float Bs[16][64];
    const int tid  = threadIdx.x;
    const int trow = tid >> 4;
    const int tcol = tid & 15;
    const int lr = tid >> 2;
    const int lk = (tid & 3) << 2;
    const int bk = tid >> 4;
    const int bn = (tid & 15) << 2;
    const float* Ab = A + (size_t)blockIdx.y * 64 * lda;
    const float* Bb = B + blockIdx.x * 64;
    const int k0 = blockIdx.z * KC;
    float acc[4][4] = {};
    for (int kt = k0; kt < k0 + KC; kt += 16) {
        float4 av = *(const float4*)(Ab + (size_t)lr * lda + kt + lk);
        if (RELU_A) {
            av.x = fmaxf(av.x, 0.f); av.y = fmaxf(av.y, 0.f);
            av.z = fmaxf(av.z, 0.f); av.w = fmaxf(av.w, 0.f);
        }
        As[lk + 0][lr] = av.x; As[lk + 1][lr] = av.y;
        As[lk + 2][lr] = av.z; As[lk + 3][lr] = av.w;
        *(float4*)&Bs[bk][bn] = *(const float4*)(Bb + (size_t)(kt + bk) * ldb + bn);
        __syncthreads();
#pragma unroll
        for (int k = 0; k < 16; k++) {
            float4 a = *(const float4*)&As[k][trow << 2];
            float4 b = *(const float4*)&Bs[k][tcol << 2];
            float ar[4] = {a.x, a.y, a.z, a.w};
            float br[4] = {b.x, b.y, b.z, b.w};
#pragma unroll
            for (int i = 0; i < 4; i++)
#pragma unroll
                for (int j = 0; j < 4; j++)
                    acc[i][j] += ar[i] * br[j];
        }
        __syncthreads();
    }
    int row0 = blockIdx.y * 64 + (trow << 2);
    int col0 = blockIdx.x * 64 + (tcol << 2);
#pragma unroll
    for (int i = 0; i < 4; i++) {
        float* cp = C + (size_t)(row0 + i) * N + col0;
        atomicAdd(cp + 0, acc[i][0]); atomicAdd(cp + 1, acc[i][1]);
        atomicAdd(cp + 2, acc[i][2]); atomicAdd(cp + 3, acc[i][3]);
    }
}

// ---------------- bias1 = (conv_bias tiled over 1280) @ mW1 (parallel) ------
__global__ void biasR1_k(const float* __restrict__ mW1,
                         const float* __restrict__ cb) {
    const int c = threadIdx.x;
    const int k0 = blockIdx.x * 8;
    float acc = 0.f;
#pragma unroll
    for (int k = k0; k < k0 + 8; k++)
        acc += cb[k & 31] * mW1[(size_t)k * 256 + c];
    atomicAdd(&g_bias1[c], acc);
}

__global__ void f1init_k(const float* __restrict__ mb1) {
    int i = blockIdx.x * 256 + threadIdx.x;
    int c = i & 255;
    g_f1[i] = g_bias1[c] + mb1[c];
}

// ---------------- message passing -------------------------------------------
__global__ void msg_root_k(const float* __restrict__ root) {
    __shared__ float Ws[2048];
    __shared__ float Xs[128 * 68];
    const int tid = threadIdx.x;
    const int n0 = blockIdx.x * 128;
    for (int i = tid; i < 512; i += 256)
        ((float4*)Ws)[i] = ((const float4*)root)[i];
    for (int idx = tid; idx < 128 * 16; idx += 256) {
        int j = idx >> 4, kq = idx & 15;
        ((float4*)(Xs + j * 68))[kq] = ((const float4*)(g_x + (size_t)(n0 + j) * 64))[kq];
    }
    __syncthreads();
    const int e0 = (tid >> 3) << 2;
    const int c0 = (tid & 7) << 2;
    float acc[4][4] = {};
#pragma unroll 4
    for (int kk = 0; kk < 64; kk += 4) {
        float4 w0 = *(const float4*)&Ws[(kk + 0) * 32 + c0];
        float4 w1 = *(const float4*)&Ws[(kk + 1) * 32 + c0];
        float4 w2 = *(const float4*)&Ws[(kk + 2) * 32 + c0];
        float4 w3 = *(const float4*)&Ws[(kk + 3) * 32 + c0];
#pragma unroll
        for (int i = 0; i < 4; i++) {
            float4 xv = *(const float4*)&Xs[(e0 + i) * 68 + kk];
            acc[i][0] += xv.x * w0.x + xv.y * w1.x + xv.z * w2.x + xv.w * w3.x;
            acc[i][1] += xv.x * w0.y + xv.y * w1.y + xv.z * w2.y + xv.w * w3.y;
            acc[i][2] += xv.x * w0.z + xv.y * w1.z + xv.z * w2.z + xv.w * w3.z;
            acc[i][3] += xv.x * w0.w + xv.y * w1.w + xv.z * w2.w + xv.w * w3.w;
        }
    }
#pragma unroll
    for (int i = 0; i < 4; i++) {
        float4 o = make_float4(acc[i][0], acc[i][1], acc[i][2], acc[i][3]);
        *(float4*)(g_dense + (size_t)(n0 + e0 + i) * 32 + c0) = o;
    }
}

__global__ void msg_combo_k(const int* __restrict__ ei) {
    __shared__ float Ws[2048];
    __shared__ float Xs[128 * 68];
    __shared__ int Srcs[128];
    __shared__ int Dsts[128];
    const int tid = threadIdx.x;
    const int c = blockIdx.x;
    const int start = g_off[c];
    const int cnt = g_hist[c];
    if (cnt == 0) return;
    const float* Wp = g_W + (size_t)c * 2048;
    for (int i = tid; i < 512; i += 256)
        ((float4*)Ws)[i] = ((const float4*)Wp)[i];

    for (int base = 0; base < cnt; base += 128) {
        int nloc = min(128, cnt - base);
        __syncthreads();
        for (int j = tid; j < nloc; j += 256) {
            int e = g_sorted[start + base + j];
            Srcs[j] = ei[e];
            Dsts[j] = ei[ETOT + e];
        }
        __syncthreads();
        for (int idx = tid; idx < nloc * 16; idx += 256) {
            int j = idx >> 4, kq = idx & 15;
            ((float4*)(Xs + j * 68))[kq] = ((const float4*)(g_x + (size_t)Srcs[j] * 64))[kq];
        }
        __syncthreads();
        const int e0 = (tid >> 3) << 2;
        const int c0 = (tid & 7) << 2;
        float acc[4][4] = {};
#pragma unroll 4
        for (int kk = 0; kk < 64; kk += 4) {
            float4 w0 = *(const float4*)&Ws[(kk + 0) * 32 + c0];
            float4 w1 = *(const float4*)&Ws[(kk + 1) * 32 + c0];
            float4 w2 = *(const float4*)&Ws[(kk + 2) * 32 + c0];
            float4 w3 = *(const float4*)&Ws[(kk + 3) * 32 + c0];
#pragma unroll
            for (int i = 0; i < 4; i++) {
                float4 xv = *(const float4*)&Xs[(e0 + i) * 68 + kk];
                acc[i][0] += xv.x * w0.x + xv.y * w1.x + xv.z * w2.x + xv.w * w3.x;
                acc[i][1] += xv.x * w0.y + xv.y * w1.y + xv.z * w2.y + xv.w * w3.y;
                acc[i][2] += xv.x * w0.z + xv.y * w1.z + xv.z * w2.z + xv.w * w3.z;
                acc[i][3] += xv.x * w0.w + xv.y * w1.w + xv.z * w2.w + xv.w * w3.w;
            }
        }
#pragma unroll
        for (int i = 0; i < 4; i++) {
            int j = e0 + i;
            if (j < nloc) {
                float* dp = &g_dense[(size_t)Dsts[j] * 32 + c0];
                atomicAdd(dp + 0, acc[i][0]); atomicAdd(dp + 1, acc[i][1]);
                atomicAdd(dp + 2, acc[i][2]); atomicAdd(dp + 3, acc[i][3]);
            }
        }
    }
}

// ---------------- readout tail: relu(f2+mb2) -> 32 -> 8 -> 1 ----------------
__global__ void head_k(const float* __restrict__ mW3, const float* __restrict__ mb3,
                       const float* __restrict__ mW4, const float* __restrict__ mb4,
                       const float* __restrict__ mW5, const float* __restrict__ mb5,
                       const float* __restrict__ mb2, float* __restrict__ out) {
    __shared__ float W3[128 * 32];
    __shared__ float W4[32 * 8];
    __shared__ float W5[8];
    __shared__ float B3[32], B4[8], B2[128], B5;
    const int tid = threadIdx.x;
    for (int i = tid; i < 4096; i += 256) W3[i] = mW3[i];
    if (tid < 256) W4[tid] = mW4[tid];
    if (tid < 128) B2[tid] = mb2[tid];
    if (tid < 32) B3[tid] = mb3[tid];
    if (tid < 8)  { W5[tid] = mW5[tid]; B4[tid] = mb4[tid]; }
    if (tid == 0) B5 = mb5[0];
    __syncthreads();
    const int warp = tid >> 5, lane = tid & 31;
    const int g = blockIdx.x * 8 + warp;
    const float* f2 = g_f2 + (size_t)g * 128;
    float acc = B3[lane];
#pragma unroll 4
    for (int k = 0; k < 128; k++) {
        float v = fmaxf(f2[k] + B2[k], 0.f);
        acc += v * W3[k * 32 + lane];
    }
    acc = fmaxf(acc, 0.f);
    float acc4 = (lane < 8) ? B4[lane] : 0.f;
#pragma unroll
    for (int k = 0; k < 32; k++) {
        float f3k = __shfl_sync(0xffffffffu, acc, k);
        if (lane < 8) acc4 += f3k * W4[k * 8 + lane];
    }
    acc4 = fmaxf(acc4, 0.f);
    float r = 0.f;
#pragma unroll
    for (int k = 0; k < 8; k++) {
        float f4k = __shfl_sync(0xffffffffu, acc4, k);
        r += f4k * W5[k];
    }
    if (lane == 0) out[g] = r + B5;
}

// ---------------- launch ----------------------------------------------------
extern "C" void kernel_launch(void* const* d_in, const int* in_sizes, int n_in,
                              void* d_out, int out_size) {
    (void)in_sizes; (void)n_in; (void)out_size;
    const int*   nf   = (const int*)d_in[0];
    const int*   ef   = (const int*)d_in[1];
    const int*   ei   = (const int*)d_in[2];
    const float* atom = (const float*)d_in[4];
    const float* bond = (const float*)d_in[5];
    const float* gW1  = (const float*)d_in[6];
    const float* gW2  = (const float*)d_in[7];
    const float* gW3  = (const float*)d_in[8];
    const float* root = (const float*)d_in[9];
    const float* cb   = (const float*)d_in[10];
    const float* mW1  = (const float*)d_in[11];
    const float* mb1  = (const float*)d_in[12];
    const float* mW2  = (const float*)d_in[13];
    const float* mb2  = (const float*)d_in[14];
    const float* mW3  = (const float*)d_in[15];
    const float* mb3  = (const float*)d_in[16];
    const float* mW4  = (const float*)d_in[17];
    const float* mb4  = (const float*)d_in[18];
    const float* mW5  = (const float*)d_in[19];
    const float* mb5  = (const float*)d_in[20];
    float* out = (float*)d_out;

    float *p_h1, *p_h2, *p_W, *p_dense, *p_f1, *p_f2, *p_b1;
    int* p_hist;
    cudaGetSymbolAddress((void**)&p_h1,    g_h1);
    cudaGetSymbolAddress((void**)&p_h2,    g_h2);
    cudaGetSymbolAddress((void**)&p_W,     g_W);
    cudaGetSymbolAddress((void**)&p_dense, g_dense);
    cudaGetSymbolAddress((void**)&p_f1,    g_f1);
    cudaGetSymbolAddress((void**)&p_f2,    g_f2);
    cudaGetSymbolAddress((void**)&p_b1,    g_bias1);
    cudaGetSymbolAddress((void**)&p_hist,  g_hist);

    static cudaStream_t s1 = nullptr, s2 = nullptr, s3 = nullptr;
    static cudaEvent_t evFork, evW, evF, evS;
    if (!s1) {
        cudaStreamCreateWithFlags(&s1, cudaStreamNonBlocking);
        cudaStreamCreateWithFlags(&s2, cudaStreamNonBlocking);
        cudaStreamCreateWithFlags(&s3, cudaStreamNonBlocking);
        cudaEventCreateWithFlags(&evFork, cudaEventDisableTiming);
        cudaEventCreateWithFlags(&evW, cudaEventDisableTiming);
        cudaEventCreateWithFlags(&evF, cudaEventDisableTiming);
        cudaEventCreateWithFlags(&evS, cudaEventDisableTiming);
    }

    cudaEventRecord(evFork, 0);
    cudaStreamWaitEvent(s1, evFork, 0);
    cudaStreamWaitEvent(s2, evFork, 0);
    cudaStreamWaitEvent(s3, evFork, 0);

    // s1: zero scratch + edge-weight MLP chain
    zero3_k<<<256, 256, 0, s1>>>((float4*)p_h2, NC * 256 / 4,
                                 (float4*)p_W,  NC * 2048 / 4,
                                 (float4*)p_f2, GTOT * 128 / 4);
    gemmE1_k<<<dim3(16, 8), 256, 0, s1>>>(bond, gW1);
    gemm_k<false><<<dim3(4, 8, 8),  256, 0, s1>>>(p_h1, gW2, p_h2, 256, 1024, 256, 128);
    gemm_k<true ><<<dim3(32, 8, 4), 256, 0, s1>>>(p_h2, gW3, p_W, 2048, 256, 2048, 64);
    cudaEventRecord(evW, s1);

    // s2: edge combo sort chain
    cudaMemsetAsync(p_hist, 0, NC * sizeof(int), s2);
    combo_k<<<ETOT / 256, 256, 0, s2>>>(ef);
    scan_k<<<1, 512, 0, s2>>>();
    scatter_k<<<ETOT / 256, 256, 0, s2>>>();
    cudaEventRecord(evS, s2);

    // s3: readout-bias precompute + f1 init
    cudaMemsetAsync(p_b1, 0, 256 * sizeof(float), s3);
    biasR1_k<<<160, 256, 0, s3>>>(mW1, cb);
    f1init_k<<<1024, 256, 0, s3>>>(mb1);
    cudaEventRecord(evF, s3);

    // main: node encode + root GEMM
    encode_x_k<<<NTOT / 4, 256>>>(nf, atom);
    msg_root_k<<<NTOT / 128, 256>>>(root);

    cudaStreamWaitEvent(0, evW, 0);
    cudaStreamWaitEvent(0, evS, 0);
    msg_combo_k<<<NC, 256>>>(ei);

    cudaStreamWaitEvent(0, evF, 0);
    gemm_k<false><<<dim3(4, 16, 10), 256>>>(p_dense, mW1, p_f1, 256, 1280, 256, 128);
    gemm_k<true ><<<dim3(2, 16, 4),  256>>>(p_f1, mW2, p_f2, 128, 256, 128, 64);
    head_k<<<GTOT / 8, 256>>>(mW3, mb3, mW4, mb4, mW5, mb5, mb2, out);
}